// round 12
// baseline (speedup 1.0000x reference)
#include <cuda_runtime.h>
#include <cuda_fp16.h>
#include <cstdint>

#define NB    2
#define SEQ   4096
#define HID   512
#define NHEAD 8
#define HDIM  64
#define BM    256
#define BN    64
#define NITER (SEQ / BN)
#define L2E   1.44269504088896340736f

typedef unsigned int u32;

// word permutation inside an 8-word (16-half) chunk: logical word w ->
// slot (w&3)*2 | (w>>2). Fragment word pairs (w, w+4) become adjacent.
#define PW(w) ((((w) & 3) << 1) | ((w) >> 2))
#define RSTR 40   // u32 words per row: 64-bit phases conflict-free

__device__ __forceinline__ u32 pack2h(float a, float b) {
    __half2 h = __floats2half2_rn(a, b);
    return *(u32*)&h;
}
__device__ __forceinline__ float ex2f(float x) {
    float y; asm("ex2.approx.ftz.f32 %0, %1;" : "=f"(y) : "f"(x)); return y;
}
// D += A @ B  (m16n8k16, fp16 in, fp32 acc)
__device__ __forceinline__ void mma16816(float* c, const u32* a, u32 b0, u32 b1) {
    asm volatile(
        "mma.sync.aligned.m16n8k16.row.col.f32.f16.f16.f32 "
        "{%0,%1,%2,%3}, {%4,%5,%6,%7}, {%8,%9}, {%0,%1,%2,%3};"
        : "+f"(c[0]), "+f"(c[1]), "+f"(c[2]), "+f"(c[3])
        : "r"(a[0]), "r"(a[1]), "r"(a[2]), "r"(a[3]), "r"(b0), "r"(b1));
}

__device__ float g_ctx[NB * SEQ * HID];

// smem word offsets (dynamic): sQ [256][40], sK [64][40], sV [64][40]
#define SQ_OFF 0
#define SK_OFF (256 * RSTR)
#define SV_OFF (SK_OFF + BN * RSTR)
#define SMEM_WORDS (SV_OFF + HDIM * RSTR)   // 15360 words = 61440 B

// ---------------------------------------------------------------------------
// Flash attention, BM=256, occ=2. Q lives in SMEM (fp16 paired layout) —
// A-frags reloaded per kcp block; K/V single-buffered, staged directly.
// Co-resident CTA hides LDG latency and overlaps HMMA/LDS/MUFU pipes.
// ---------------------------------------------------------------------------
__global__ void __launch_bounds__(256, 2)
attn_kernel(const float* __restrict__ Q, const float* __restrict__ K,
            const float* __restrict__ V, const float* __restrict__ sigma,
            const float* __restrict__ lam_p)
{
    extern __shared__ u32 smem[];
    u32* sQ = smem + SQ_OFF;                          // [256][RSTR]
    u32 (*sK)[RSTR] = (u32(*)[RSTR])(smem + SK_OFF);  // [token][chunked d]
    u32 (*sV)[RSTR] = (u32(*)[RSTR])(smem + SV_OFF);  // [d][chunked token]

    const int tid  = threadIdx.x;
    const int warp = tid >> 5;
    const int lane = tid & 31;
    const int r    = lane >> 2;
    const int c    = lane & 3;

    const int bb = blockIdx.y >> 3;
    const int hh = blockIdx.y & 7;
    const int qbase = blockIdx.x * BM;

    float sc = fminf(fmaxf(sigma[bb], 0.001f), 0.2f);
    float sn = (sc - 0.001f) * (1.0f / 0.199f);
    const float rC = lam_p[0] * 0.1f * sn * (1.0f / ((float)SEQ * (float)SEQ)) * L2E;

    const float* Qb = Q + (size_t)bb * SEQ * HID + hh * HDIM;
    const float* Kb = K + (size_t)bb * SEQ * HID + hh * HDIM;
    const float* Vb = V + (size_t)bb * SEQ * HID + hh * HDIM;

    const int k_tok  = tid >> 2;          // K staging: token row
    const int k_part = tid & 3;           // K staging: chunk
    const int v_p    = tid & 31;          // V staging: token pair
    const int v_d0   = (tid >> 5) * 8;    // V staging: 8 d's
    const int v_w    = (v_p >> 3) * 8 + PW(v_p & 7);

    // ---- stage this CTA's Q tile (fp16, scaled, PW layout): row = tid
    {
        const float s = 0.125f * L2E;
        const float* qr = Qb + (size_t)(qbase + tid) * HID;
        u32* dst = &sQ[tid * RSTR];
        #pragma unroll
        for (int ch = 0; ch < 4; ch++) {
            #pragma unroll
            for (int j = 0; j < 4; j++) {
                float4 v = ((const float4*)qr)[ch * 4 + j];
                dst[ch * 8 + PW(2 * j)]     = pack2h(v.x * s, v.y * s);
                dst[ch * 8 + PW(2 * j + 1)] = pack2h(v.z * s, v.w * s);
            }
        }
    }

    float oacc[2][8][4];
    #pragma unroll
    for (int mf = 0; mf < 2; mf++)
        #pragma unroll
        for (int i = 0; i < 8; i++)
            #pragma unroll
            for (int j = 0; j < 4; j++) oacc[mf][i][j] = 0.0f;
    float lsum[2][2] = {{0.0f, 0.0f}, {0.0f, 0.0f}};

    const int w32 = warp * 32;   // warp's q-row base within tile

    for (int kt = 0; kt < NITER; kt++) {
        const int kbase = kt * BN;

        __syncthreads();   // previous tile's compute done (Q visible on kt=0)

        // ---- stage K tile [64 tok x 64 d] (PW layout)
        {
            const float* kr = Kb + (size_t)(kbase + k_tok) * HID + k_part * 16;
            u32* row = &sK[k_tok][k_part * 8];
            #pragma unroll
            for (int i = 0; i < 4; i++) {
                float4 v = ((const float4*)kr)[i];
                row[PW(2 * i)]     = pack2h(v.x, v.y);
                row[PW(2 * i + 1)] = pack2h(v.z, v.w);
            }
        }
        // ---- stage V^T tile [64 d x 64 tok] (token pairs packed)
        {
            const float* v0 = Vb + (size_t)(kbase + 2 * v_p) * HID + v_d0;
            const float* v1 = v0 + HID;
            #pragma unroll
            for (int i = 0; i < 2; i++) {
                float4 a = ((const float4*)v0)[i];
                float4 b = ((const float4*)v1)[i];
                float av[4] = {a.x, a.y, a.z, a.w};
                float bv[4] = {b.x, b.y, b.z, b.w};
                #pragma unroll
                for (int k2 = 0; k2 < 4; k2++) {
                    sV[v_d0 + i * 4 + k2][v_w] = pack2h(av[k2], bv[k2]);
                }
            }
        }
        __syncthreads();

        // ---- 4 blocks: QK(2 n-frags, Q from SMEM) -> softmax -> PV chunk
        #pragma unroll
        for (int kcp = 0; kcp < 4; kcp++) {
            float sacc[2][2][4];
            #pragma unroll
            for (int mf = 0; mf < 2; mf++)
                #pragma unroll
                for (int h = 0; h < 2; h++)
                    #pragma unroll
                    for (int j = 0; j < 4; j++) sacc[mf][h][j] = 0.0f;

            #pragma unroll
            for (int kc = 0; kc < 4; kc++) {
                const int kw = kc * 8 + 2 * c;
                // A-frags from SMEM Q (2 LDS.64 per m-frag)
                uint2 qa0 = *(const uint2*)&sQ[(w32 + r) * RSTR + kw];
                uint2 qa8 = *(const uint2*)&sQ[(w32 + 8 + r) * RSTR + kw];
                uint2 qb0 = *(const uint2*)&sQ[(w32 + 16 + r) * RSTR + kw];
                uint2 qb8 = *(const uint2*)&sQ[(w32 + 24 + r) * RSTR + kw];
                u32 aq0[4] = {qa0.x, qa8.x, qa0.y, qa8.y};
                u32 aq1[4] = {qb0.x, qb8.x, qb0.y, qb8.y};
                #pragma unroll
                for (int h = 0; h < 2; h++) {
                    const int nt = kcp * 2 + h;
                    uint2 bbv = *(const uint2*)&sK[nt * 8 + r][kw];
                    mma16816(sacc[0][h], aq0, bbv.x, bbv.y);
                    mma16816(sacc[1][h], aq1, bbv.x, bbv.y);
                }
            }

            // softmax for these 16 token columns
            u32 pah[2][4];
            #pragma unroll
            for (int mf = 0; mf < 2; mf++) {
                const float fi0 = (float)(qbase + w32 + mf * 16 + r);
                const float fi1 = fi0 + 8.0f;
                #pragma unroll
                for (int h = 0; h < 2; h++) {
                    const float jb = (float)(kbase + (kcp * 2 + h) * 8 + 2 * c);
                    float d00 = fi0 - jb, d01 = d00 - 1.0f;
                    float d10 = fi1 - jb, d11 = d10 - 1.0f;
                    float p00 = ex2f(fmaf(-rC * d00, d00, sacc[mf][h][0]));
                    float p01 = ex2f(fmaf(-rC * d01, d01, sacc[mf][h][1]));
                    float p10 = ex2f(fmaf(-rC * d10, d10, sacc[mf][h][2]));
                    float p11 = ex2f(fmaf(-rC * d11, d11, sacc[mf][h][3]));
                    lsum[mf][0] += p00 + p01;
                    lsum[mf][1] += p10 + p11;
                    pah[mf][h * 2 + 0] = pack2h(p00, p01);
                    pah[mf][h * 2 + 1] = pack2h(p10, p11);
                }
            }

            // PV for this 16-token chunk
            const int kw = kcp * 8 + 2 * c;
            #pragma unroll
            for (int ntv = 0; ntv < 8; ntv++) {
                uint2 bbv = *(const uint2*)&sV[ntv * 8 + r][kw];
                mma16816(oacc[0][ntv], pah[0], bbv.x, bbv.y);
                mma16816(oacc[1][ntv], pah[1], bbv.x, bbv.y);
            }
        }
    }

    // ---- reduce l, normalize, store ctx
    #pragma unroll
    for (int mf = 0; mf < 2; mf++) {
        float l0 = lsum[mf][0], l1 = lsum[mf][1];
        l0 += __shfl_xor_sync(0xffffffffu, l0, 1);
        l0 += __shfl_xor_sync(0xffffffffu, l0, 2);
        l1 += __shfl_xor_sync(0xffffffffu, l1, 1);
        l1 += __shfl_xor_sync(0xffffffffu, l1, 2);
        const float inv0 = 1.0f / l0;
        const float inv1 = 1.0f / l1;

        const int row0 = qbase + w32 + mf * 16 + r;
        float* g0 = g_ctx + ((size_t)bb * SEQ + row0) * HID + hh * HDIM + 2 * c;
        float* g1 = g0 + 8 * HID;
        #pragma unroll
        for (int ntv = 0; ntv < 8; ntv++) {
            *(float2*)(g0 + ntv * 8) =
                make_float2(oacc[mf][ntv][0] * inv0, oacc[mf][ntv][1] * inv0);
            *(float2*)(g1 + ntv * 8) =
                make_float2(oacc[mf][ntv][2] * inv1, oacc[mf][ntv][3] * inv1);
        }
    }
}

// ---------------------------------------------------------------------------
// out = ctx @ W^T + b  (M=8192, N=512, K=512) — single-pass fp16 HMMA.
// Proven round-9 version: 128x128 tile, PCH=32, PSTR=40 halfs.
// ---------------------------------------------------------------------------
#define PCH 32
#define PSTR 40

__global__ void __launch_bounds__(256, 2)
proj_kernel(const float* __restrict__ W, const float* __restrict__ bias,
            float* __restrict__ out)
{
    __shared__ __align__(16) __half sA[128][PSTR];
    __shared__ __align__(16) __half sW[128][PSTR];

    const int tid  = threadIdx.x;
    const int warp = tid >> 5;
    const int lane = tid & 31;
    const int r    = lane >> 2;
    const int c    = lane & 3;
    const int mw   = warp & 3;
    const int nw   = warp >> 2;

    const int mbase = blockIdx.x * 128;
    const int nbase = blockIdx.y * 128;

    const int r2 = tid >> 1;
    const int h2 = (tid & 1) * 16;

    float acc[2][8][4];
    #pragma unroll
    for (int mf = 0; mf < 2; mf++)
        #pragma unroll
        for (int nf = 0; nf < 8; nf++)
            #pragma unroll
            for (int j = 0; j < 4; j++) acc[mf][nf][j] = 0.0f;

    for (int kc = 0; kc < HID / PCH; kc++) {
        const int k0 = kc * PCH;
        __syncthreads();
        {
            const float* ar = g_ctx + (size_t)(mbase + r2) * HID + k0 + h2;
            #pragma unroll
            for (int i = 0; i < 4; i++) {
                float4 v = ((const float4*)ar)[i];
                *(u32*)&sA[r2][h2 + i * 4]     = pack2h(v.x, v.y);
                *(u32*)&sA[r2][h2 + i * 4 + 2] = pack2h(v.z, v.w);
            }
            const float* wr = W + (size_t)(nbase + r2) * HID + k0 + h2;
            #pragma unroll
            for (int i = 0; i < 4; i++) {
                float4 v = ((const float4*)wr)[i];
                *(u32*)&sW[r2][h2 + i * 4]     = pack2h(v.x, v.y);
                *(u32*)&sW[r2][h2 + i * 4 + 2] = pack2h(v.z, v.w);
            }
        }
        __syncthreads();

        #pragma unroll
        for (int kf = 0; kf < 2; kf++) {
            const int kk = kf * 16 + 2 * c;
            u32 ah[2][4];
            #pragma unroll
            for (int mf = 0; mf < 2; mf++) {
                const int m0 = mw * 32 + mf * 16;
                ah[mf][0] = *(const u32*)&sA[m0 + r][kk];
                ah[mf][1] = *(const u32*)&sA[m0 + r + 8][kk];
                ah[mf][2] = *(const u32*)&sA[m0 + r][kk + 8];
                ah[mf][3] = *(const u32*)&sA[m0 + r + 8][kk + 8];
            }
            #pragma unroll
            for (int nf = 0; nf < 8; nf++) {
                const int n0 = nw * 64 + nf * 8 + r;
                u32 b0 = *(const u32*)&sW[n0][kk];
                u32 b1 = *(const u32*)&sW[n0][kk + 8];
                mma16816(acc[0][nf], ah[0], b0, b1);
                mma16816(acc[1][nf], ah[1], b0, b1);
            }
        }
    }

    #pragma unroll
    for (int nf = 0; nf < 8; nf++) {
        const int n = nbase + nw * 64 + nf * 8 + 2 * c;
        const float bv0 = bias[n], bv1 = bias[n + 1];
        #pragma unroll
        for (int mf = 0; mf < 2; mf++) {
            const int m = mbase + mw * 32 + mf * 16 + r;
            *(float2*)&out[(size_t)m * HID + n] =
                make_float2(acc[mf][nf][0] + bv0, acc[mf][nf][1] + bv1);
            *(float2*)&out[(size_t)(m + 8) * HID + n] =
                make_float2(acc[mf][nf][2] + bv0, acc[mf][nf][3] + bv1);
        }
    }
}

extern "C" void kernel_launch(void* const* d_in, const int* in_sizes, int n_in,
                              void* d_out, int out_size)
{
    const float* Q     = (const float*)d_in[0];
    const float* K     = (const float*)d_in[1];
    const float* V     = (const float*)d_in[2];
    const float* sigma = (const float*)d_in[3];
    const float* lam   = (const float*)d_in[4];
    const float* W     = (const float*)d_in[5];
    const float* bias  = (const float*)d_in[6];
    float* out = (float*)d_out;

    cudaFuncSetAttribute(attn_kernel, cudaFuncAttributeMaxDynamicSharedMemorySize,
                         SMEM_WORDS * (int)sizeof(u32));

    dim3 g1(SEQ / BM, NB * NHEAD);
    attn_kernel<<<g1, 256, SMEM_WORDS * sizeof(u32)>>>(Q, K, V, sigma, lam);

    dim3 g2(NB * SEQ / 128, HID / 128);
    proj_kernel<<<g2, 256>>>(W, bias, out);
}

// round 13
// speedup vs baseline: 1.1268x; 1.1268x over previous
#include <cuda_runtime.h>
#include <cuda_fp16.h>
#include <cstdint>

#define NB    2
#define SEQ   4096
#define HID   512
#define NHEAD 8
#define HDIM  64
#define BM    256
#define BN    64
#define NITER (SEQ / BN)
#define L2E   1.44269504088896340736f

typedef unsigned int u32;

// word permutation inside an 8-word (16-half) chunk: logical word w ->
// slot (w&3)*2 | (w>>2). Fragment word pairs (w, w+4) become adjacent
// -> one LDS.64 per B-fragment.
#define PW(w) ((((w) & 3) << 1) | ((w) >> 2))
#define RSTR 40   // u32 words per row: 64-bit phases conflict-free

__device__ __forceinline__ u32 pack2h(float a, float b) {
    __half2 h = __floats2half2_rn(a, b);
    return *(u32*)&h;
}
__device__ __forceinline__ float ex2f(float x) {
    float y; asm("ex2.approx.ftz.f32 %0, %1;" : "=f"(y) : "f"(x)); return y;
}
// D += A @ B  (m16n8k16, fp16 in, fp32 acc)
__device__ __forceinline__ void mma16816(float* c, const u32* a, u32 b0, u32 b1) {
    asm volatile(
        "mma.sync.aligned.m16n8k16.row.col.f32.f16.f16.f32 "
        "{%0,%1,%2,%3}, {%4,%5,%6,%7}, {%8,%9}, {%0,%1,%2,%3};"
        : "+f"(c[0]), "+f"(c[1]), "+f"(c[2]), "+f"(c[3])
        : "r"(a[0]), "r"(a[1]), "r"(a[2]), "r"(a[3]), "r"(b0), "r"(b1));
}

__device__ float g_ctx[NB * SEQ * HID];

// ---------------------------------------------------------------------------
// Flash attention, BM=256, occ=2. Q frags persistent in registers (r11
// structure); K/V single-buffered (20 KB), staged gmem->cvt->STS inline.
// h-outer QK shrinks sacc to 8 regs; __launch_bounds__(256,2) -> 2 CTAs/SM
// so one CTA's softmax/staging overlaps the other's HMMA/LDS, and 256 CTAs
// fit one wave (296 slots).
// ---------------------------------------------------------------------------
__global__ void __launch_bounds__(256, 2)
attn_kernel(const float* __restrict__ Q, const float* __restrict__ K,
            const float* __restrict__ V, const float* __restrict__ sigma,
            const float* __restrict__ lam_p)
{
    __shared__ __align__(16) u32 sK[BN][RSTR];     // [token][chunked d]
    __shared__ __align__(16) u32 sV[HDIM][RSTR];   // [d][chunked token]

    const int tid  = threadIdx.x;
    const int warp = tid >> 5;
    const int lane = tid & 31;
    const int r    = lane >> 2;
    const int c    = lane & 3;

    const int bb = blockIdx.y >> 3;
    const int hh = blockIdx.y & 7;
    const int qbase = blockIdx.x * BM;

    float sc = fminf(fmaxf(sigma[bb], 0.001f), 0.2f);
    float sn = (sc - 0.001f) * (1.0f / 0.199f);
    const float rC = lam_p[0] * 0.1f * sn * (1.0f / ((float)SEQ * (float)SEQ)) * L2E;

    const float* Kb = K + (size_t)bb * SEQ * HID + hh * HDIM;
    const float* Vb = V + (size_t)bb * SEQ * HID + hh * HDIM;

    const int k_tok  = tid >> 2;          // K staging: token row
    const int k_part = tid & 3;           // K staging: chunk
    const int v_p    = tid & 31;          // V staging: token pair
    const int v_d0   = (tid >> 5) * 8;    // V staging: 8 d's
    const int v_w    = (v_p >> 3) * 8 + PW(v_p & 7);

    // ---- Q fragments (persistent): 2 m-frags x 16 words, scaled
    u32 qf[2][16];
    {
        const float* Qb = Q + (size_t)bb * SEQ * HID + hh * HDIM;
        const float s = 0.125f * L2E;
        #pragma unroll
        for (int mf = 0; mf < 2; mf++) {
            const int row0 = qbase + warp * 32 + mf * 16 + r;
            const float* q0 = Qb + (size_t)row0 * HID;
            const float* q1 = q0 + 8 * HID;
            #pragma unroll
            for (int kc = 0; kc < 4; kc++) {
                int d = kc * 16 + 2 * c;
                qf[mf][kc * 4 + 0] = pack2h(q0[d] * s,     q0[d + 1] * s);
                qf[mf][kc * 4 + 1] = pack2h(q1[d] * s,     q1[d + 1] * s);
                qf[mf][kc * 4 + 2] = pack2h(q0[d + 8] * s, q0[d + 9] * s);
                qf[mf][kc * 4 + 3] = pack2h(q1[d + 8] * s, q1[d + 9] * s);
            }
        }
    }

    float oacc[2][8][4];
    #pragma unroll
    for (int mf = 0; mf < 2; mf++)
        #pragma unroll
        for (int i = 0; i < 8; i++)
            #pragma unroll
            for (int j = 0; j < 4; j++) oacc[mf][i][j] = 0.0f;
    float lsum[2][2] = {{0.0f, 0.0f}, {0.0f, 0.0f}};

    const int w32 = warp * 32;

    for (int kt = 0; kt < NITER; kt++) {
        const int kbase = kt * BN;

        __syncthreads();   // previous tile's fragment reads done

        // ---- stage K tile [64 tok x 64 d] (PW layout), gmem->cvt->STS
        {
            const float* kr = Kb + (size_t)(kbase + k_tok) * HID + k_part * 16;
            u32* row = &sK[k_tok][k_part * 8];
            #pragma unroll
            for (int i = 0; i < 4; i++) {
                float4 v = ((const float4*)kr)[i];
                row[PW(2 * i)]     = pack2h(v.x, v.y);
                row[PW(2 * i + 1)] = pack2h(v.z, v.w);
            }
        }
        // ---- stage V^T tile [64 d x 64 tok] (token pairs packed)
        {
            const float* v0 = Vb + (size_t)(kbase + 2 * v_p) * HID + v_d0;
            const float* v1 = v0 + HID;
            #pragma unroll
            for (int i = 0; i < 2; i++) {
                float4 a = ((const float4*)v0)[i];
                float4 b = ((const float4*)v1)[i];
                float av[4] = {a.x, a.y, a.z, a.w};
                float bv[4] = {b.x, b.y, b.z, b.w};
                #pragma unroll
                for (int k2 = 0; k2 < 4; k2++) {
                    sV[v_d0 + i * 4 + k2][v_w] = pack2h(av[k2], bv[k2]);
                }
            }
        }
        __syncthreads();

        // ---- 4 blocks: QK (h-outer, sacc=8 regs) -> softmax -> PV chunk
        #pragma unroll
        for (int kcp = 0; kcp < 4; kcp++) {
            u32 pah[2][4];

            #pragma unroll
            for (int h = 0; h < 2; h++) {
                const int nt = kcp * 2 + h;
                float sacc[2][4];
                #pragma unroll
                for (int mf = 0; mf < 2; mf++)
                    #pragma unroll
                    for (int j = 0; j < 4; j++) sacc[mf][j] = 0.0f;

                #pragma unroll
                for (int kc = 0; kc < 4; kc++) {
                    const int kw = kc * 8 + 2 * c;
                    uint2 bbv = *(const uint2*)&sK[nt * 8 + r][kw];
                    mma16816(sacc[0], &qf[0][kc * 4], bbv.x, bbv.y);
                    mma16816(sacc[1], &qf[1][kc * 4], bbv.x, bbv.y);
                }

                const float jb = (float)(kbase + nt * 8 + 2 * c);
                #pragma unroll
                for (int mf = 0; mf < 2; mf++) {
                    const float fi0 = (float)(qbase + w32 + mf * 16 + r);
                    const float fi1 = fi0 + 8.0f;
                    float d00 = fi0 - jb, d01 = d00 - 1.0f;
                    float d10 = fi1 - jb, d11 = d10 - 1.0f;
                    float p00 = ex2f(fmaf(-rC * d00, d00, sacc[mf][0]));
                    float p01 = ex2f(fmaf(-rC * d01, d01, sacc[mf][1]));
                    float p10 = ex2f(fmaf(-rC * d10, d10, sacc[mf][2]));
                    float p11 = ex2f(fmaf(-rC * d11, d11, sacc[mf][3]));
                    lsum[mf][0] += p00 + p01;
                    lsum[mf][1] += p10 + p11;
                    pah[mf][h * 2 + 0] = pack2h(p00, p01);
                    pah[mf][h * 2 + 1] = pack2h(p10, p11);
                }
            }

            // PV for this 16-token chunk
            const int kw = kcp * 8 + 2 * c;
            #pragma unroll
            for (int ntv = 0; ntv < 8; ntv++) {
                uint2 bbv = *(const uint2*)&sV[ntv * 8 + r][kw];
                mma16816(oacc[0][ntv], pah[0], bbv.x, bbv.y);
                mma16816(oacc[1][ntv], pah[1], bbv.x, bbv.y);
            }
        }
    }

    // ---- reduce l, normalize, store ctx
    #pragma unroll
    for (int mf = 0; mf < 2; mf++) {
        float l0 = lsum[mf][0], l1 = lsum[mf][1];
        l0 += __shfl_xor_sync(0xffffffffu, l0, 1);
        l0 += __shfl_xor_sync(0xffffffffu, l0, 2);
        l1 += __shfl_xor_sync(0xffffffffu, l1, 1);
        l1 += __shfl_xor_sync(0xffffffffu, l1, 2);
        const float inv0 = 1.0f / l0;
        const float inv1 = 1.0f / l1;

        const int row0 = qbase + w32 + mf * 16 + r;
        float* g0 = g_ctx + ((size_t)bb * SEQ + row0) * HID + hh * HDIM + 2 * c;
        float* g1 = g0 + 8 * HID;
        #pragma unroll
        for (int ntv = 0; ntv < 8; ntv++) {
            *(float2*)(g0 + ntv * 8) =
                make_float2(oacc[mf][ntv][0] * inv0, oacc[mf][ntv][1] * inv0);
            *(float2*)(g1 + ntv * 8) =
                make_float2(oacc[mf][ntv][2] * inv1, oacc[mf][ntv][3] * inv1);
        }
    }
}

// ---------------------------------------------------------------------------
// out = ctx @ W^T + b  (M=8192, N=512, K=512) — single-pass fp16 HMMA.
// Proven round-9 version: 128x128 tile, PCH=32, PSTR=40 halfs.
// ---------------------------------------------------------------------------
#define PCH 32
#define PSTR 40

__global__ void __launch_bounds__(256, 2)
proj_kernel(const float* __restrict__ W, const float* __restrict__ bias,
            float* __restrict__ out)
{
    __shared__ __align__(16) __half sA[128][PSTR];
    __shared__ __align__(16) __half sW[128][PSTR];

    const int tid  = threadIdx.x;
    const int warp = tid >> 5;
    const int lane = tid & 31;
    const int r    = lane >> 2;
    const int c    = lane & 3;
    const int mw   = warp & 3;
    const int nw   = warp >> 2;

    const int mbase = blockIdx.x * 128;
    const int nbase = blockIdx.y * 128;

    const int r2 = tid >> 1;
    const int h2 = (tid & 1) * 16;

    float acc[2][8][4];
    #pragma unroll
    for (int mf = 0; mf < 2; mf++)
        #pragma unroll
        for (int nf = 0; nf < 8; nf++)
            #pragma unroll
            for (int j = 0; j < 4; j++) acc[mf][nf][j] = 0.0f;

    for (int kc = 0; kc < HID / PCH; kc++) {
        const int k0 = kc * PCH;
        __syncthreads();
        {
            const float* ar = g_ctx + (size_t)(mbase + r2) * HID + k0 + h2;
            #pragma unroll
            for (int i = 0; i < 4; i++) {
                float4 v = ((const float4*)ar)[i];
                *(u32*)&sA[r2][h2 + i * 4]     = pack2h(v.x, v.y);
                *(u32*)&sA[r2][h2 + i * 4 + 2] = pack2h(v.z, v.w);
            }
            const float* wr = W + (size_t)(nbase + r2) * HID + k0 + h2;
            #pragma unroll
            for (int i = 0; i < 4; i++) {
                float4 v = ((const float4*)wr)[i];
                *(u32*)&sW[r2][h2 + i * 4]     = pack2h(v.x, v.y);
                *(u32*)&sW[r2][h2 + i * 4 + 2] = pack2h(v.z, v.w);
            }
        }
        __syncthreads();

        #pragma unroll
        for (int kf = 0; kf < 2; kf++) {
            const int kk = kf * 16 + 2 * c;
            u32 ah[2][4];
            #pragma unroll
            for (int mf = 0; mf < 2; mf++) {
                const int m0 = mw * 32 + mf * 16;
                ah[mf][0] = *(const u32*)&sA[m0 + r][kk];
                ah[mf][1] = *(const u32*)&sA[m0 + r + 8][kk];
                ah[mf][2] = *(const u32*)&sA[m0 + r][kk + 8];
                ah[mf][3] = *(const u32*)&sA[m0 + r + 8][kk + 8];
            }
            #pragma unroll
            for (int nf = 0; nf < 8; nf++) {
                const int n0 = nw * 64 + nf * 8 + r;
                u32 b0 = *(const u32*)&sW[n0][kk];
                u32 b1 = *(const u32*)&sW[n0][kk + 8];
                mma16816(acc[0][nf], ah[0], b0, b1);
                mma16816(acc[1][nf], ah[1], b0, b1);
            }
        }
    }

    #pragma unroll
    for (int nf = 0; nf < 8; nf++) {
        const int n = nbase + nw * 64 + nf * 8 + 2 * c;
        const float bv0 = bias[n], bv1 = bias[n + 1];
        #pragma unroll
        for (int mf = 0; mf < 2; mf++) {
            const int m = mbase + mw * 32 + mf * 16 + r;
            *(float2*)&out[(size_t)m * HID + n] =
                make_float2(acc[mf][nf][0] + bv0, acc[mf][nf][1] + bv1);
            *(float2*)&out[(size_t)(m + 8) * HID + n] =
                make_float2(acc[mf][nf][2] + bv0, acc[mf][nf][3] + bv1);
        }
    }
}

extern "C" void kernel_launch(void* const* d_in, const int* in_sizes, int n_in,
                              void* d_out, int out_size)
{
    const float* Q     = (const float*)d_in[0];
    const float* K     = (const float*)d_in[1];
    const float* V     = (const float*)d_in[2];
    const float* sigma = (const float*)d_in[3];
    const float* lam   = (const float*)d_in[4];
    const float* W     = (const float*)d_in[5];
    const float* bias  = (const float*)d_in[6];
    float* out = (float*)d_out;

    dim3 g1(SEQ / BM, NB * NHEAD);
    attn_kernel<<<g1, 256>>>(Q, K, V, sigma, lam);

    dim3 g2(NB * SEQ / 128, HID / 128);
    proj_kernel<<<g2, 256>>>(W, bias, out);
}